// round 1
// baseline (speedup 1.0000x reference)
#include <cuda_runtime.h>
#include <cstdint>

#define BB 8
#define DD 128
#define SS 4096
#define BM 64
#define BN 64

// Scratch for Q, K, V: (B, S, D) row-major, fp32. 16 MB each.
__device__ float g_Q[BB * SS * DD];
__device__ float g_K[BB * SS * DD];
__device__ float g_V[BB * SS * DD];

// ---------------------------------------------------------------------------
// QKV projection: out[b][s][e] = sum_d x[b][d][s] * W[e][d] + bias[e]
// grid: (S/BM, B, 3)  block: 256
// smem: XsT[128][64] (d-major x tile), WsT[128][129] (d-major W, padded)
// ---------------------------------------------------------------------------
__global__ __launch_bounds__(256) void qkv_kernel(
    const float* __restrict__ x,
    const float* __restrict__ Wq, const float* __restrict__ bq,
    const float* __restrict__ Wk, const float* __restrict__ bk,
    const float* __restrict__ Wv, const float* __restrict__ bv)
{
    extern __shared__ float sm[];
    float (*XsT)[BM]  = (float(*)[BM])sm;                 // [128][64]
    float (*WsT)[129] = (float(*)[129])(sm + DD * BM);    // [128][129]

    const int s0 = blockIdx.x * BM;
    const int b  = blockIdx.y;
    const int z  = blockIdx.z;
    const float* W    = (z == 0) ? Wq : (z == 1) ? Wk : Wv;
    const float* bias = (z == 0) ? bq : (z == 1) ? bk : bv;
    float* out        = (z == 0) ? g_Q : (z == 1) ? g_K : g_V;

    const int tid = threadIdx.x;

    // Load x tile transposed: XsT[d][sl] = x[b][d][s0+sl]  (coalesced in sl)
    for (int i = tid; i < DD * BM; i += 256) {
        int d = i >> 6, sl = i & 63;
        XsT[d][sl] = x[((size_t)b * DD + d) * SS + s0 + sl];
    }
    // Load W transposed: WsT[d][e] = W[e][d]  (coalesced in d)
    for (int i = tid; i < DD * DD; i += 256) {
        int e = i >> 7, d = i & 127;
        WsT[d][e] = W[i];
    }
    __syncthreads();

    const int r = tid >> 4;   // row group: rows r, r+16, r+32, r+48
    const int c = tid & 15;   // col group: cols c, c+16, ..., c+112

    float acc[4][8];
#pragma unroll
    for (int i = 0; i < 4; i++)
#pragma unroll
        for (int j = 0; j < 8; j++) acc[i][j] = 0.0f;

#pragma unroll 4
    for (int d = 0; d < DD; d++) {
        float a[4], wv[8];
#pragma unroll
        for (int i = 0; i < 4; i++) a[i] = XsT[d][r + 16 * i];
#pragma unroll
        for (int j = 0; j < 8; j++) wv[j] = WsT[d][c + 16 * j];
#pragma unroll
        for (int i = 0; i < 4; i++)
#pragma unroll
            for (int j = 0; j < 8; j++) acc[i][j] = fmaf(a[i], wv[j], acc[i][j]);
    }

#pragma unroll
    for (int i = 0; i < 4; i++) {
        size_t row = ((size_t)b * SS + s0 + r + 16 * i) * DD;
#pragma unroll
        for (int j = 0; j < 8; j++) {
            int e = c + 16 * j;
            out[row + e] = acc[i][j] + bias[e];
        }
    }
}

// ---------------------------------------------------------------------------
// Flash attention + residual, output in (B, D, S) layout.
// grid: (S/BM, B)  block: 256
// smem: QsT[128][65], KsT[128][65], Vs[64][128], Ss[64][65]
// ---------------------------------------------------------------------------
__global__ __launch_bounds__(256) void attn_kernel(
    const float* __restrict__ x, float* __restrict__ out)
{
    extern __shared__ float sm[];
    float (*QsT)[65] = (float(*)[65])sm;                       // [128][65]
    float (*KsT)[65] = (float(*)[65])(sm + 128 * 65);          // [128][65]
    float (*Vs)[DD]  = (float(*)[DD])(sm + 2 * 128 * 65);      // [64][128]
    float (*Ss)[65]  = (float(*)[65])(sm + 2 * 128 * 65 + BN * DD); // [64][65]

    const int s0  = blockIdx.x * BM;
    const int b   = blockIdx.y;
    const int tid = threadIdx.x;
    const float scale = 0.08838834764831845f;  // 1/sqrt(128)

    // Load Q tile transposed & pre-scaled: QsT[d][sl]
    for (int i = tid; i < BM * DD; i += 256) {
        int sl = i >> 7, d = i & 127;
        QsT[d][sl] = g_Q[((size_t)b * SS + s0 + sl) * DD + d] * scale;
    }

    const int r = tid >> 4;   // query rows: r, r+16, r+32, r+48
    const int c = tid & 15;   // key cols / out cols groups

    float o[4][8];
    float m_i[4], l_i[4];
#pragma unroll
    for (int i = 0; i < 4; i++) {
        m_i[i] = -1e30f;
        l_i[i] = 0.0f;
#pragma unroll
        for (int j = 0; j < 8; j++) o[i][j] = 0.0f;
    }

    for (int j0 = 0; j0 < SS; j0 += BN) {
        __syncthreads();  // protect KsT/Vs/Ss from previous iteration readers
        // Load K tile transposed, V tile direct (both coalesced)
        for (int i = tid; i < BN * DD; i += 256) {
            int sl = i >> 7, d = i & 127;
            KsT[d][sl] = g_K[((size_t)b * SS + j0 + sl) * DD + d];
        }
        for (int i = tid; i < BN * DD; i += 256) {
            ((float*)Vs)[i] = g_V[((size_t)b * SS + j0) * DD + i];
        }
        __syncthreads();

        // S = Q K^T  (4x4 micro-tile, strided by 16)
        float s[4][4];
#pragma unroll
        for (int i = 0; i < 4; i++)
#pragma unroll
            for (int j = 0; j < 4; j++) s[i][j] = 0.0f;

#pragma unroll 4
        for (int d = 0; d < DD; d++) {
            float a[4], kk[4];
#pragma unroll
            for (int i = 0; i < 4; i++) a[i] = QsT[d][r + 16 * i];
#pragma unroll
            for (int j = 0; j < 4; j++) kk[j] = KsT[d][c + 16 * j];
#pragma unroll
            for (int i = 0; i < 4; i++)
#pragma unroll
                for (int j = 0; j < 4; j++) s[i][j] = fmaf(a[i], kk[j], s[i][j]);
        }

        // Row max across the 16 lanes sharing each row group
        float mt[4];
#pragma unroll
        for (int i = 0; i < 4; i++) {
            mt[i] = fmaxf(fmaxf(s[i][0], s[i][1]), fmaxf(s[i][2], s[i][3]));
        }
#pragma unroll
        for (int m = 8; m >= 1; m >>= 1)
#pragma unroll
            for (int i = 0; i < 4; i++)
                mt[i] = fmaxf(mt[i], __shfl_xor_sync(0xffffffffu, mt[i], m));

        float alpha[4];
#pragma unroll
        for (int i = 0; i < 4; i++) {
            float mn = fmaxf(m_i[i], mt[i]);
            alpha[i] = __expf(m_i[i] - mn);
            m_i[i] = mn;
        }

        float lt[4];
#pragma unroll
        for (int i = 0; i < 4; i++) {
            lt[i] = 0.0f;
#pragma unroll
            for (int j = 0; j < 4; j++) {
                s[i][j] = __expf(s[i][j] - m_i[i]);
                lt[i] += s[i][j];
            }
        }
#pragma unroll
        for (int m = 8; m >= 1; m >>= 1)
#pragma unroll
            for (int i = 0; i < 4; i++)
                lt[i] += __shfl_xor_sync(0xffffffffu, lt[i], m);

#pragma unroll
        for (int i = 0; i < 4; i++) {
            l_i[i] = l_i[i] * alpha[i] + lt[i];
#pragma unroll
            for (int j = 0; j < 8; j++) o[i][j] *= alpha[i];
        }

        // Write P to smem for the PV GEMM
#pragma unroll
        for (int i = 0; i < 4; i++)
#pragma unroll
            for (int j = 0; j < 4; j++) Ss[r + 16 * i][c + 16 * j] = s[i][j];
        __syncthreads();

        // O += P @ V  (4x8 micro-tile)
#pragma unroll 2
        for (int k = 0; k < BN; k++) {
            float pa[4], vb[8];
#pragma unroll
            for (int i = 0; i < 4; i++) pa[i] = Ss[r + 16 * i][k];
#pragma unroll
            for (int j = 0; j < 8; j++) vb[j] = Vs[k][c + 16 * j];
#pragma unroll
            for (int i = 0; i < 4; i++)
#pragma unroll
                for (int j = 0; j < 8; j++) o[i][j] = fmaf(pa[i], vb[j], o[i][j]);
        }
    }

    // Normalize, stage through smem (reuse QsT as [e][sl]), then coalesced
    // write with fused residual into (B, D, S) layout.
    __syncthreads();
    float (*OT)[65] = QsT;
#pragma unroll
    for (int i = 0; i < 4; i++) {
        float inv_l = 1.0f / l_i[i];
#pragma unroll
        for (int j = 0; j < 8; j++)
            OT[c + 16 * j][r + 16 * i] = o[i][j] * inv_l;
    }
    __syncthreads();

    for (int i = tid; i < DD * BM; i += 256) {
        int e = i >> 6, sl = i & 63;
        size_t gi = ((size_t)b * DD + e) * SS + s0 + sl;
        out[gi] = OT[e][sl] + x[gi];
    }
}

// ---------------------------------------------------------------------------
extern "C" void kernel_launch(void* const* d_in, const int* in_sizes, int n_in,
                              void* d_out, int out_size)
{
    const float* x  = (const float*)d_in[0];
    const float* Wq = (const float*)d_in[1];
    const float* bq = (const float*)d_in[2];
    const float* Wk = (const float*)d_in[3];
    const float* bk = (const float*)d_in[4];
    const float* Wv = (const float*)d_in[5];
    const float* bv = (const float*)d_in[6];
    float* out = (float*)d_out;

    const int qkv_smem  = (DD * BM + DD * 129) * (int)sizeof(float);         // 98,816 B
    const int attn_smem = (2 * 128 * 65 + BN * DD + BM * 65) * (int)sizeof(float); // 115,968 B

    cudaFuncSetAttribute(qkv_kernel,  cudaFuncAttributeMaxDynamicSharedMemorySize, qkv_smem);
    cudaFuncSetAttribute(attn_kernel, cudaFuncAttributeMaxDynamicSharedMemorySize, attn_smem);

    dim3 qkv_grid(SS / BM, BB, 3);
    qkv_kernel<<<qkv_grid, 256, qkv_smem>>>(x, Wq, bq, Wk, bk, Wv, bv);

    dim3 attn_grid(SS / BM, BB);
    attn_kernel<<<attn_grid, 256, attn_smem>>>(x, out);
}

// round 2
// speedup vs baseline: 4.0565x; 4.0565x over previous
#include <cuda_runtime.h>
#include <cstdint>

#define BB 8
#define DD 128
#define SS 4096
#define BM 128      // queries per CTA (8 warps x 16 rows)
#define BN 64       // keys per inner tile

// Scratch for Q, K, V: (B, S, D) row-major, fp32. 16 MB each.
__device__ float g_Q[BB * SS * DD];
__device__ float g_K[BB * SS * DD];
__device__ float g_V[BB * SS * DD];

// ---------------------------------------------------------------------------
// QKV projection (unchanged from R1): out[b][s][e] = sum_d x[b][d][s]*W[e][d]+b
// ---------------------------------------------------------------------------
__global__ __launch_bounds__(256) void qkv_kernel(
    const float* __restrict__ x,
    const float* __restrict__ Wq, const float* __restrict__ bq,
    const float* __restrict__ Wk, const float* __restrict__ bk,
    const float* __restrict__ Wv, const float* __restrict__ bv)
{
    extern __shared__ float sm[];
    float (*XsT)[64]  = (float(*)[64])sm;                 // [128][64]
    float (*WsT)[129] = (float(*)[129])(sm + DD * 64);    // [128][129]

    const int s0 = blockIdx.x * 64;
    const int b  = blockIdx.y;
    const int z  = blockIdx.z;
    const float* W    = (z == 0) ? Wq : (z == 1) ? Wk : Wv;
    const float* bias = (z == 0) ? bq : (z == 1) ? bk : bv;
    float* out        = (z == 0) ? g_Q : (z == 1) ? g_K : g_V;

    const int tid = threadIdx.x;

    for (int i = tid; i < DD * 64; i += 256) {
        int d = i >> 6, sl = i & 63;
        XsT[d][sl] = x[((size_t)b * DD + d) * SS + s0 + sl];
    }
    for (int i = tid; i < DD * DD; i += 256) {
        int e = i >> 7, d = i & 127;
        WsT[d][e] = W[i];
    }
    __syncthreads();

    const int r = tid >> 4;
    const int c = tid & 15;

    float acc[4][8];
#pragma unroll
    for (int i = 0; i < 4; i++)
#pragma unroll
        for (int j = 0; j < 8; j++) acc[i][j] = 0.0f;

#pragma unroll 4
    for (int d = 0; d < DD; d++) {
        float a[4], wv[8];
#pragma unroll
        for (int i = 0; i < 4; i++) a[i] = XsT[d][r + 16 * i];
#pragma unroll
        for (int j = 0; j < 8; j++) wv[j] = WsT[d][c + 16 * j];
#pragma unroll
        for (int i = 0; i < 4; i++)
#pragma unroll
            for (int j = 0; j < 8; j++) acc[i][j] = fmaf(a[i], wv[j], acc[i][j]);
    }

#pragma unroll
    for (int i = 0; i < 4; i++) {
        size_t row = ((size_t)b * SS + s0 + r + 16 * i) * DD;
#pragma unroll
        for (int j = 0; j < 8; j++) {
            int e = c + 16 * j;
            out[row + e] = acc[i][j] + bias[e];
        }
    }
}

// ---------------------------------------------------------------------------
// tf32 helpers
// ---------------------------------------------------------------------------
__device__ __forceinline__ unsigned f2tf(float f) {
    unsigned u;
    asm("cvt.rna.tf32.f32 %0, %1;" : "=r"(u) : "f"(f));
    return u;
}

__device__ __forceinline__ void mma8(float c[4],
    unsigned a0, unsigned a1, unsigned a2, unsigned a3,
    unsigned b0, unsigned b1)
{
    asm volatile(
        "mma.sync.aligned.m16n8k8.row.col.f32.tf32.tf32.f32 "
        "{%0,%1,%2,%3},{%4,%5,%6,%7},{%8,%9},{%0,%1,%2,%3};"
        : "+f"(c[0]), "+f"(c[1]), "+f"(c[2]), "+f"(c[3])
        : "r"(a0), "r"(a1), "r"(a2), "r"(a3), "r"(b0), "r"(b1));
}

// Smem layout (floats). Fragment rows are 132 floats (33 float4) so that
// consecutive rows rotate banks by 4 -> conflict-free producer STS and
// conflict-free consumer LDS.128 (lane-linear float4).
#define QA_OFF 0
#define QA_SZ  (128 * 132)           // [warp*16+kstep][lane*4+j]
#define KB_OFF (QA_OFF + QA_SZ)
#define KB_SZ  (64 * 132)            // [nt*8+kpair][lane*4+j]
#define VB_OFF (KB_OFF + KB_SZ)
#define VB_SZ  (64 * 132)            // [dnt*4+kpair][lane*4+j]
#define ATTN_SMEM ((QA_OFF + QA_SZ + KB_SZ + VB_SZ) * 4)

// ---------------------------------------------------------------------------
// Flash attention with tf32 mma.sync + residual, output (B, D, S).
// grid: (S/BM, B)  block: 256 (8 warps, 16 query rows each)
// ---------------------------------------------------------------------------
__global__ __launch_bounds__(256, 1) void attn_kernel(
    const float* __restrict__ x, float* __restrict__ out)
{
    extern __shared__ float sm[];
    float* qA = sm + QA_OFF;
    float* kB = sm + KB_OFF;
    float* vB = sm + VB_OFF;
    const uint4* qA4 = (const uint4*)qA;
    const uint4* kB4 = (const uint4*)kB;
    const uint4* vB4 = (const uint4*)vB;

    const int tid = threadIdx.x;
    const int w   = tid >> 5;
    const int t   = tid & 31;
    const int s0  = blockIdx.x * BM;
    const int b   = blockIdx.y;
    const float scale = 0.08838834764831845f;  // 1/sqrt(128)

    // ---- Load Q tile into fragment-major smem (pre-scaled, tf32) ----
    const float* Qg = g_Q + ((size_t)b * SS + s0) * DD;
    for (int i = tid; i < BM * 32; i += 256) {
        int row = i >> 5, dg = i & 31;
        float4 v = *(const float4*)(Qg + row * DD + dg * 4);
        float vv[4] = {v.x, v.y, v.z, v.w};
#pragma unroll
        for (int c = 0; c < 4; c++) {
            int d = dg * 4 + c;
            int dst = (((row >> 4) * 16 + (d >> 3)) * 132)
                    + ((((row & 7) << 2) | (d & 3)) << 2)
                    + (((row >> 3) & 1) | (((d >> 2) & 1) << 1));
            qA[dst] = __uint_as_float(f2tf(vv[c] * scale));
        }
    }

    // ---- Accumulators ----
    float o[16][4];
#pragma unroll
    for (int i = 0; i < 16; i++)
#pragma unroll
        for (int j = 0; j < 4; j++) o[i][j] = 0.0f;
    float m0 = -1e30f, m1 = -1e30f, l0 = 0.0f, l1 = 0.0f;

    const float* Kg = g_K + (size_t)b * SS * DD;
    const float* Vg = g_V + (size_t)b * SS * DD;

    const int lane0 = (t & 28) | ((t & 3) >> 1);
    const int lane2 = lane0 + 2;

    for (int j0 = 0; j0 < SS; j0 += BN) {
        __syncthreads();
        // ---- Load K, V tiles into fragment-major smem (tf32) ----
        for (int i = tid; i < BN * 32; i += 256) {
            int key = i >> 5, dg = i & 31;
            float4 kv = *(const float4*)(Kg + (size_t)(j0 + key) * DD + dg * 4);
            float kk[4] = {kv.x, kv.y, kv.z, kv.w};
#pragma unroll
            for (int c = 0; c < 4; c++) {
                int d = dg * 4 + c;
                int dst = (((key >> 3) * 8 + (d >> 4)) * 132)
                        + ((((key & 7) << 2) | (d & 3)) << 2)
                        + (((d >> 2) & 1) | (((d >> 3) & 1) << 1));
                kB[dst] = __uint_as_float(f2tf(kk[c]));
            }
            float4 vv4 = *(const float4*)(Vg + (size_t)(j0 + key) * DD + dg * 4);
            float vvv[4] = {vv4.x, vv4.y, vv4.z, vv4.w};
#pragma unroll
            for (int c = 0; c < 4; c++) {
                int d = dg * 4 + c;
                int dst = (((d >> 3) * 4 + (key >> 4)) * 132)
                        + ((((d & 7) << 2) | (key & 3)) << 2)
                        + (((key >> 2) & 1) | (((key >> 3) & 1) << 1));
                vB[dst] = __uint_as_float(f2tf(vvv[c]));
            }
        }
        __syncthreads();

        // ---- S = Q K^T  (m16 x n64 x k128 per warp) ----
        float s_[8][4];
#pragma unroll
        for (int nt = 0; nt < 8; nt++)
#pragma unroll
            for (int j = 0; j < 4; j++) s_[nt][j] = 0.0f;

        const uint4* qb = qA4 + (w * 16) * 33 + t;
#pragma unroll
        for (int kp = 0; kp < 8; kp++) {
            uint4 aE = qb[(2 * kp) * 33];
            uint4 aO = qb[(2 * kp + 1) * 33];
#pragma unroll
            for (int nt = 0; nt < 8; nt++) {
                uint4 bb = kB4[(nt * 8 + kp) * 33 + t];
                mma8(s_[nt], aE.x, aE.y, aE.z, aE.w, bb.x, bb.y);
                mma8(s_[nt], aO.x, aO.y, aO.z, aO.w, bb.z, bb.w);
            }
        }

        // ---- Online softmax (rows t/4 and t/4+8 of this warp) ----
        float mr0 = -1e30f, mr1 = -1e30f;
#pragma unroll
        for (int nt = 0; nt < 8; nt++) {
            mr0 = fmaxf(mr0, fmaxf(s_[nt][0], s_[nt][1]));
            mr1 = fmaxf(mr1, fmaxf(s_[nt][2], s_[nt][3]));
        }
        mr0 = fmaxf(mr0, __shfl_xor_sync(0xffffffffu, mr0, 1));
        mr0 = fmaxf(mr0, __shfl_xor_sync(0xffffffffu, mr0, 2));
        mr1 = fmaxf(mr1, __shfl_xor_sync(0xffffffffu, mr1, 1));
        mr1 = fmaxf(mr1, __shfl_xor_sync(0xffffffffu, mr1, 2));

        float mn0 = fmaxf(m0, mr0), mn1 = fmaxf(m1, mr1);
        float al0 = __expf(m0 - mn0), al1 = __expf(m1 - mn1);
        m0 = mn0; m1 = mn1;

        float lr0 = 0.0f, lr1 = 0.0f;
#pragma unroll
        for (int nt = 0; nt < 8; nt++) {
            s_[nt][0] = __expf(s_[nt][0] - mn0);
            s_[nt][1] = __expf(s_[nt][1] - mn0);
            s_[nt][2] = __expf(s_[nt][2] - mn1);
            s_[nt][3] = __expf(s_[nt][3] - mn1);
            lr0 += s_[nt][0] + s_[nt][1];
            lr1 += s_[nt][2] + s_[nt][3];
        }
        lr0 += __shfl_xor_sync(0xffffffffu, lr0, 1);
        lr0 += __shfl_xor_sync(0xffffffffu, lr0, 2);
        lr1 += __shfl_xor_sync(0xffffffffu, lr1, 1);
        lr1 += __shfl_xor_sync(0xffffffffu, lr1, 2);
        l0 = l0 * al0 + lr0;
        l1 = l1 * al1 + lr1;

#pragma unroll
        for (int nt2 = 0; nt2 < 16; nt2++) {
            o[nt2][0] *= al0; o[nt2][1] *= al0;
            o[nt2][2] *= al1; o[nt2][3] *= al1;
        }

        // ---- O += P @ V  (m16 x n128 x k64) ----
#pragma unroll
        for (int kp2 = 0; kp2 < 4; kp2++) {
            unsigned pa[2][4];
#pragma unroll
            for (int e = 0; e < 2; e++) {
                int nt = 2 * kp2 + e;
                unsigned u0 = f2tf(s_[nt][0]);
                unsigned u1 = f2tf(s_[nt][1]);
                unsigned u2 = f2tf(s_[nt][2]);
                unsigned u3 = f2tf(s_[nt][3]);
                unsigned x0 = __shfl_sync(0xffffffffu, u0, lane0);
                unsigned x1 = __shfl_sync(0xffffffffu, u1, lane0);
                unsigned y0 = __shfl_sync(0xffffffffu, u2, lane0);
                unsigned y1 = __shfl_sync(0xffffffffu, u3, lane0);
                unsigned z0 = __shfl_sync(0xffffffffu, u0, lane2);
                unsigned z1 = __shfl_sync(0xffffffffu, u1, lane2);
                unsigned v0 = __shfl_sync(0xffffffffu, u2, lane2);
                unsigned v1 = __shfl_sync(0xffffffffu, u3, lane2);
                pa[e][0] = (t & 1) ? x1 : x0;
                pa[e][1] = (t & 1) ? y1 : y0;
                pa[e][2] = (t & 1) ? z1 : z0;
                pa[e][3] = (t & 1) ? v1 : v0;
            }
#pragma unroll
            for (int nt2 = 0; nt2 < 16; nt2++) {
                uint4 bb = vB4[(nt2 * 4 + kp2) * 33 + t];
                mma8(o[nt2], pa[0][0], pa[0][1], pa[0][2], pa[0][3], bb.x, bb.y);
                mma8(o[nt2], pa[1][0], pa[1][1], pa[1][2], pa[1][3], bb.z, bb.w);
            }
        }
    }

    // ---- Epilogue: normalize, transpose via smem, fused residual ----
    float inv0 = 1.0f / l0, inv1 = 1.0f / l1;
    __syncthreads();
    float* Os = sm;  // reuse (128 d rows x stride 129)
    int R0 = w * 16 + (t >> 2), R1 = R0 + 8;
#pragma unroll
    for (int nt2 = 0; nt2 < 16; nt2++) {
        int d0 = nt2 * 8 + 2 * (t & 3);
        Os[d0 * 129 + R0]       = o[nt2][0] * inv0;
        Os[(d0 + 1) * 129 + R0] = o[nt2][1] * inv0;
        Os[d0 * 129 + R1]       = o[nt2][2] * inv1;
        Os[(d0 + 1) * 129 + R1] = o[nt2][3] * inv1;
    }
    __syncthreads();

    for (int i = tid; i < 128 * 32; i += 256) {
        int d = i >> 5, sg = i & 31;
        size_t gi = ((size_t)b * DD + d) * SS + s0 + sg * 4;
        float4 xv = *(const float4*)(x + gi);
        float4 ov;
        ov.x = Os[d * 129 + sg * 4 + 0] + xv.x;
        ov.y = Os[d * 129 + sg * 4 + 1] + xv.y;
        ov.z = Os[d * 129 + sg * 4 + 2] + xv.z;
        ov.w = Os[d * 129 + sg * 4 + 3] + xv.w;
        *(float4*)(out + gi) = ov;
    }
}

// ---------------------------------------------------------------------------
extern "C" void kernel_launch(void* const* d_in, const int* in_sizes, int n_in,
                              void* d_out, int out_size)
{
    const float* x  = (const float*)d_in[0];
    const float* Wq = (const float*)d_in[1];
    const float* bq = (const float*)d_in[2];
    const float* Wk = (const float*)d_in[3];
    const float* bk = (const float*)d_in[4];
    const float* Wv = (const float*)d_in[5];
    const float* bv = (const float*)d_in[6];
    float* out = (float*)d_out;

    const int qkv_smem = (DD * 64 + DD * 129) * (int)sizeof(float);

    cudaFuncSetAttribute(qkv_kernel,  cudaFuncAttributeMaxDynamicSharedMemorySize, qkv_smem);
    cudaFuncSetAttribute(attn_kernel, cudaFuncAttributeMaxDynamicSharedMemorySize, ATTN_SMEM);

    dim3 qkv_grid(SS / 64, BB, 3);
    qkv_kernel<<<qkv_grid, 256, qkv_smem>>>(x, Wq, bq, Wk, bk, Wv, bv);

    dim3 attn_grid(SS / BM, BB);
    attn_kernel<<<attn_grid, 256, ATTN_SMEM>>>(x, out);
}